// round 1
// baseline (speedup 1.0000x reference)
#include <cuda_runtime.h>
#include <cuda_bf16.h>
#include <math_constants.h>

// Problem constants
#define BATCH   2
#define SEQ     2048
#define HIDDEN  1024
#define HEADS   16
#define HEAD_D  64
#define QKV_N   (3 * HIDDEN)          // 3072
#define M_TOT   (BATCH * SEQ)         // 4096
#define ATTN_SCALE 125.0f             // TEMP_K / sqrt(HEAD_D) = 1000/8

// Scratch (allocation-free rule: __device__ globals)
__device__ float g_qkv[M_TOT * QKV_N];   // 48 MB: [b*S+s][3072] = c*1024 + h*64 + d
__device__ float g_ctx[M_TOT * HIDDEN];  // 16 MB: [b*S+s][h*64+d]

// ---------------------------------------------------------------------------
// Tiled fp32 GEMM with bias: C[M,N] = A[M,K] @ B[K,N] + bias[N]
// BM=BN=128, BK=8, 256 threads, 8x8 micro-tile per thread.
// All problem dims are multiples of 128/8 -> no edge guards.
// ---------------------------------------------------------------------------
__global__ __launch_bounds__(256)
void sgemm_bias(const float* __restrict__ A, const float* __restrict__ B,
                const float* __restrict__ bias, float* __restrict__ C,
                int M, int N, int K)
{
    const int BM = 128, BN = 128, BK = 8;
    __shared__ float As[BK][BM];      // transposed A tile
    __shared__ float Bs[BK][BN];

    int tid = threadIdx.x;
    int bx = blockIdx.x;              // N tile
    int by = blockIdx.y;              // M tile
    int ty = tid >> 4;                // 0..15
    int tx = tid & 15;                // 0..15

    // A-tile load mapping: 128 rows x 8 cols = 256 float4
    int arow = tid >> 1;              // 0..127
    int acol = (tid & 1) * 4;         // 0 or 4
    // B-tile load mapping: 8 rows x 128 cols = 256 float4
    int brow = tid >> 5;              // 0..7
    int bcol = (tid & 31) * 4;        // 0..124

    const float* Aptr = A + (size_t)(by * BM + arow) * K + acol;
    const float* Bptr = B + (size_t)brow * N + bx * BN + bcol;

    float acc[8][8];
    #pragma unroll
    for (int i = 0; i < 8; i++)
        #pragma unroll
        for (int j = 0; j < 8; j++) acc[i][j] = 0.0f;

    for (int k0 = 0; k0 < K; k0 += BK) {
        float4 a4 = *(const float4*)(Aptr + k0);
        float4 b4 = *(const float4*)(Bptr + (size_t)k0 * N);

        As[acol + 0][arow] = a4.x;
        As[acol + 1][arow] = a4.y;
        As[acol + 2][arow] = a4.z;
        As[acol + 3][arow] = a4.w;
        *(float4*)&Bs[brow][bcol] = b4;
        __syncthreads();

        #pragma unroll
        for (int k = 0; k < BK; k++) {
            float ra[8], rb[8];
            #pragma unroll
            for (int i = 0; i < 4; i++) {
                float4 t = *(const float4*)&As[k][ty * 8 + i * 4];
                ra[i * 4 + 0] = t.x; ra[i * 4 + 1] = t.y;
                ra[i * 4 + 2] = t.z; ra[i * 4 + 3] = t.w;
            }
            #pragma unroll
            for (int j = 0; j < 2; j++) {
                float4 t = *(const float4*)&As[k][ty * 8 + j * 4];
                (void)t; // (kept simple; real loads above)
            }
            #pragma unroll
            for (int j = 0; j < 2; j++) {
                float4 t = *(const float4*)&Bs[k][tx * 8 + j * 4];
                rb[j * 4 + 0] = t.x; rb[j * 4 + 1] = t.y;
                rb[j * 4 + 2] = t.z; rb[j * 4 + 3] = t.w;
            }
            #pragma unroll
            for (int i = 0; i < 8; i++)
                #pragma unroll
                for (int j = 0; j < 8; j++)
                    acc[i][j] += ra[i] * rb[j];
        }
        __syncthreads();
    }

    // Epilogue: add bias, store
    #pragma unroll
    for (int i = 0; i < 8; i++) {
        int row = by * BM + ty * 8 + i;
        float* crow = C + (size_t)row * N + bx * BN + tx * 8;
        const float* brow_bias = bias + bx * BN + tx * 8;
        #pragma unroll
        for (int j4 = 0; j4 < 2; j4++) {
            float4 o;
            o.x = acc[i][j4 * 4 + 0] + brow_bias[j4 * 4 + 0];
            o.y = acc[i][j4 * 4 + 1] + brow_bias[j4 * 4 + 1];
            o.z = acc[i][j4 * 4 + 2] + brow_bias[j4 * 4 + 2];
            o.w = acc[i][j4 * 4 + 3] + brow_bias[j4 * 4 + 3];
            *(float4*)(crow + j4 * 4) = o;
        }
    }
}

// ---------------------------------------------------------------------------
// Causal flash attention, fp32, online softmax.
// grid = (SEQ/64, HEADS, BATCH), block = 64 threads.
// Thread t owns query row (qt*64 + t): q[64] in registers (pre-scaled by 125),
// acc[64] in registers. K/V 64x64 tiles staged in padded smem (broadcast reads).
// ---------------------------------------------------------------------------
#define KV_PAD 68   // row stride in floats (16B-aligned, kills store conflicts)

__global__ __launch_bounds__(64)
void attn_kernel(const float* __restrict__ qkv, float* __restrict__ ctx)
{
    __shared__ float ks[64][KV_PAD];
    __shared__ float vs[64][KV_PAD];

    int qt = blockIdx.x;
    int h  = blockIdx.y;
    int b  = blockIdx.z;
    int t  = threadIdx.x;
    int srow = qt * 64 + t;

    const float* qrow = qkv + (size_t)(b * SEQ + srow) * QKV_N + h * HEAD_D;

    float q[HEAD_D];
    #pragma unroll
    for (int d = 0; d < HEAD_D; d += 4) {
        float4 v4 = *(const float4*)(qrow + d);
        q[d + 0] = v4.x * ATTN_SCALE;
        q[d + 1] = v4.y * ATTN_SCALE;
        q[d + 2] = v4.z * ATTN_SCALE;
        q[d + 3] = v4.w * ATTN_SCALE;
    }

    float acc[HEAD_D];
    #pragma unroll
    for (int d = 0; d < HEAD_D; d++) acc[d] = 0.0f;
    float m = -CUDART_INF_F;
    float l = 0.0f;

    for (int kt = 0; kt <= qt; kt++) {
        __syncthreads();   // protect previous tile before overwrite
        // cooperative tile load: thread t loads K/V row (kt*64 + t)
        const float* krow = qkv + (size_t)(b * SEQ + kt * 64 + t) * QKV_N
                          + HIDDEN + h * HEAD_D;
        const float* vrow = krow + HIDDEN;
        #pragma unroll
        for (int d = 0; d < HEAD_D; d += 4) {
            *(float4*)&ks[t][d] = *(const float4*)(krow + d);
            *(float4*)&vs[t][d] = *(const float4*)(vrow + d);
        }
        __syncthreads();

        int jmax = (kt == qt) ? t : 63;   // causal bound within tile
        for (int j = 0; j <= jmax; j++) {
            float s = 0.0f;
            #pragma unroll
            for (int d = 0; d < HEAD_D; d += 4) {
                float4 k4 = *(const float4*)&ks[j][d];
                s += q[d + 0] * k4.x;
                s += q[d + 1] * k4.y;
                s += q[d + 2] * k4.z;
                s += q[d + 3] * k4.w;
            }
            float mn   = fmaxf(m, s);
            float corr = __expf(m - mn);   // exp(-inf)=0 handles first step
            float p    = __expf(s - mn);
            l = l * corr + p;
            #pragma unroll
            for (int d = 0; d < HEAD_D; d += 4) {
                float4 v4 = *(const float4*)&vs[j][d];
                acc[d + 0] = acc[d + 0] * corr + p * v4.x;
                acc[d + 1] = acc[d + 1] * corr + p * v4.y;
                acc[d + 2] = acc[d + 2] * corr + p * v4.z;
                acc[d + 3] = acc[d + 3] * corr + p * v4.w;
            }
            m = mn;
        }
    }

    float inv = 1.0f / l;
    float* out = ctx + (size_t)(b * SEQ + srow) * HIDDEN + h * HEAD_D;
    #pragma unroll
    for (int d = 0; d < HEAD_D; d += 4) {
        float4 o;
        o.x = acc[d + 0] * inv;
        o.y = acc[d + 1] * inv;
        o.z = acc[d + 2] * inv;
        o.w = acc[d + 3] * inv;
        *(float4*)(out + d) = o;
    }
}

// ---------------------------------------------------------------------------
extern "C" void kernel_launch(void* const* d_in, const int* in_sizes, int n_in,
                              void* d_out, int out_size)
{
    const float* x     = (const float*)d_in[0];
    const float* W_qkv = (const float*)d_in[1];
    const float* b_qkv = (const float*)d_in[2];
    const float* W_out = (const float*)d_in[3];
    const float* b_out = (const float*)d_in[4];
    float* out = (float*)d_out;

    float* qkv; float* ctx;
    cudaGetSymbolAddress((void**)&qkv, g_qkv);
    cudaGetSymbolAddress((void**)&ctx, g_ctx);

    // 1) QKV projection: [4096,1024] @ [1024,3072] + bias
    {
        dim3 grid(QKV_N / 128, M_TOT / 128);
        sgemm_bias<<<grid, 256>>>(x, W_qkv, b_qkv, qkv, M_TOT, QKV_N, HIDDEN);
    }
    // 2) Causal attention
    {
        dim3 grid(SEQ / 64, HEADS, BATCH);
        attn_kernel<<<grid, 64>>>(qkv, ctx);
    }
    // 3) Output projection: [4096,1024] @ [1024,1024] + bias
    {
        dim3 grid(HIDDEN / 128, M_TOT / 128);
        sgemm_bias<<<grid, 256>>>(ctx, W_out, b_out, out, M_TOT, HIDDEN, HIDDEN);
    }
}